// round 8
// baseline (speedup 1.0000x reference)
#include <cuda_runtime.h>

// KGAT neighbor attention, algebraically folded.
//
// Identity 1: no activation between fc1 and fc2 ->
//   logits = concat @ (W1 @ W2) + const.  v = W1@W2 = [v1|v2|v3].
// Identity 2: softmax over k is shift-invariant; e.v1 + c is constant over
//   k -> attention weights depend ONLY on ne_k.v2 + nr_k.v3.
// So: att = softmax_k(ne_k.v2 + nr_k.v3), out = [e, sum_k att_k * ne_k].
//
// Kernel 1: warp-per-output fold of v2,v3 (coalesced, one wave).
// Kernel 2: PERSISTENT streaming kernel: exactly 148*5 blocks (one full
// residency wave, no tail-wave quantization), warp-level grid-stride over
// pairs. v2/v3 hoisted out of the loop. Stores at loop-body end so the 11
// independent LDG.128s of each iteration front-batch.

#define D        128
#define K        5
#define WARPS_PER_BLOCK 8
#define THREADS  (WARPS_PER_BLOCK * 32)
#define NUM_SMS  148
#define BLOCKS_PER_SM 5
#define PERSIST_BLOCKS (NUM_SMS * BLOCKS_PER_SM)          // 740
#define PERSIST_WARPS  (PERSIST_BLOCKS * WARPS_PER_BLOCK) // 5920

__device__ __align__(16) float g_v[256];   // v2 (128) | v3 (128)

__device__ __forceinline__ float warp_sum(float x) {
    #pragma unroll
    for (int o = 16; o > 0; o >>= 1)
        x += __shfl_xor_sync(0xffffffffu, x, o);
    return x;
}

__device__ __forceinline__ float dot4(float4 a, float4 b) {
    return fmaf(a.x, b.x, fmaf(a.y, b.y, fmaf(a.z, b.z, a.w * b.w)));
}

// One warp per output element f (0..255): folds rows 128..383 of W1 with W2.
// (Rows 0..127 = v1 are unused: softmax is invariant to the e.v1 + c shift.)
__global__ void __launch_bounds__(THREADS)
fold_mlp_kernel(const float* __restrict__ W1,   // [384, 128] row-major
                const float* __restrict__ W2)   // [128, 1]
{
    const int warp = (blockIdx.x * blockDim.x + threadIdx.x) >> 5;
    const int lane = threadIdx.x & 31;
    if (warp >= 256) return;

    const float4 w2 = __ldg(reinterpret_cast<const float4*>(W2) + lane);
    const float4 a  = __ldg(reinterpret_cast<const float4*>(W1 + (size_t)(warp + 128) * 128) + lane);
    const float s = warp_sum(dot4(a, w2));
    if (lane == 0) g_v[warp] = s;
}

__global__ void __launch_bounds__(THREADS, BLOCKS_PER_SM)
kgat_kernel(const float* __restrict__ ent,     // [P, 128]
            const float* __restrict__ ne,      // [P, K, 128]
            const float* __restrict__ nr,      // [P, K, 128]
            float* __restrict__ out,           // [P, 256]
            int total_pairs)
{
    const int warp0 = (blockIdx.x * blockDim.x + threadIdx.x) >> 5;
    const int lane  = threadIdx.x & 31;

    // Folded weight vectors: loaded once per warp, live across the loop
    const float4* vp = reinterpret_cast<const float4*>(g_v);
    const float4 v2 = __ldg(vp + lane);
    const float4 v3 = __ldg(vp + 32 + lane);

    for (int p = warp0; p < total_pairs; p += PERSIST_WARPS) {
        // Streaming data: zero reuse -> evict-first (.cs).
        // All 11 loads independent -> front-batched (MLP=11 per iteration).
        const float4* ep  = reinterpret_cast<const float4*>(ent + (size_t)p * D);
        const float4* nep = reinterpret_cast<const float4*>(ne + (size_t)p * (K * D));
        const float4* nrp = reinterpret_cast<const float4*>(nr + (size_t)p * (K * D));

        const float4 e4 = __ldcs(ep + lane);

        float4 nek[K];
        float  logit[K];
        #pragma unroll
        for (int k = 0; k < K; k++) {
            nek[k]          = __ldcs(nep + k * 32 + lane);
            const float4 r4 = __ldcs(nrp + k * 32 + lane);
            logit[k] = dot4(nek[k], v2) + dot4(r4, v3);
        }
        #pragma unroll
        for (int k = 0; k < K; k++)
            logit[k] = warp_sum(logit[k]);   // every lane has all K logits

        // Softmax over K=5 (fp32)
        float m = logit[0];
        #pragma unroll
        for (int k = 1; k < K; k++) m = fmaxf(m, logit[k]);
        float ex[K], sum = 0.0f;
        #pragma unroll
        for (int k = 0; k < K; k++) { ex[k] = __expf(logit[k] - m); sum += ex[k]; }
        const float inv = 1.0f / sum;

        // Weighted sum of neighbor entity embeddings
        float4 acc = make_float4(0.f, 0.f, 0.f, 0.f);
        #pragma unroll
        for (int k = 0; k < K; k++) {
            const float a = ex[k] * inv;
            acc.x = fmaf(a, nek[k].x, acc.x);
            acc.y = fmaf(a, nek[k].y, acc.y);
            acc.z = fmaf(a, nek[k].z, acc.z);
            acc.w = fmaf(a, nek[k].w, acc.w);
        }

        // Output: [e | neigh_att]; stores at the end of the iteration
        float4* op = reinterpret_cast<float4*>(out + (size_t)p * (2 * D));
        __stcs(op + lane, e4);
        __stcs(op + 32 + lane, acc);
    }
}

extern "C" void kernel_launch(void* const* d_in, const int* in_sizes, int n_in,
                              void* d_out, int out_size) {
    const float* ent = (const float*)d_in[0];   // entity_embedding   [B,N,128]
    const float* ne  = (const float*)d_in[1];   // neigh_entity       [B,N,5,128]
    const float* nr  = (const float*)d_in[2];   // neigh_relation     [B,N,5,128]
    const float* W1  = (const float*)d_in[3];   // [384,128]
    const float* W2  = (const float*)d_in[5];   // [128,1]
    float* out = (float*)d_out;

    const int total_pairs = in_sizes[0] / D;    // B*N

    // 256 warps needed -> 32 blocks of 8 warps
    fold_mlp_kernel<<<32, THREADS>>>(W1, W2);

    kgat_kernel<<<PERSIST_BLOCKS, THREADS>>>(ent, ne, nr, out, total_pairs);
}

// round 9
// speedup vs baseline: 1.0739x; 1.0739x over previous
#include <cuda_runtime.h>

// KGAT neighbor attention, algebraically folded.
//
// Identity 1: no activation between fc1 and fc2 ->
//   logits = concat @ (W1 @ W2) + const.  v = W1@W2 = [v1|v2|v3].
// Identity 2: softmax over k is shift-invariant; e.v1 + c is constant over
//   k -> attention weights depend ONLY on ne_k.v2 + nr_k.v3.
// So: att = softmax_k(ne_k.v2 + nr_k.v3), out = [e, sum_k att_k * ne_k].
//
// Kernel 1: warp-per-output fold of v2,v3 (coalesced, one wave).
// Kernel 2: persistent (444 blocks = 148 SM x 3, no tail wave), each warp
// processes TWO pairs per iteration with all 22 LDG.128 front-batched, so
// iteration-boundary compute bubbles are halved and the 10 warp-reductions
// interleave (ILP). Stores at iteration end.

#define D        128
#define K        5
#define WARPS_PER_BLOCK 8
#define THREADS  (WARPS_PER_BLOCK * 32)
#define NUM_SMS  148
#define BLOCKS_PER_SM 3
#define PERSIST_BLOCKS (NUM_SMS * BLOCKS_PER_SM)          // 444
#define PERSIST_WARPS  (PERSIST_BLOCKS * WARPS_PER_BLOCK) // 3552

__device__ __align__(16) float g_v[256];   // v2 (128) | v3 (128)

__device__ __forceinline__ float warp_sum(float x) {
    #pragma unroll
    for (int o = 16; o > 0; o >>= 1)
        x += __shfl_xor_sync(0xffffffffu, x, o);
    return x;
}

__device__ __forceinline__ float dot4(float4 a, float4 b) {
    return fmaf(a.x, b.x, fmaf(a.y, b.y, fmaf(a.z, b.z, a.w * b.w)));
}

// One warp per output element f (0..255): folds rows 128..383 of W1 with W2.
__global__ void __launch_bounds__(THREADS)
fold_mlp_kernel(const float* __restrict__ W1,   // [384, 128] row-major
                const float* __restrict__ W2)   // [128, 1]
{
    const int warp = (blockIdx.x * blockDim.x + threadIdx.x) >> 5;
    const int lane = threadIdx.x & 31;
    if (warp >= 256) return;

    const float4 w2 = __ldg(reinterpret_cast<const float4*>(W2) + lane);
    const float4 a  = __ldg(reinterpret_cast<const float4*>(W1 + (size_t)(warp + 128) * 128) + lane);
    const float s = warp_sum(dot4(a, w2));
    if (lane == 0) g_v[warp] = s;
}

// Process one pair's reduction/softmax/output given its preloaded registers.
__device__ __forceinline__ void finish_pair(
    const float4 e4, float4 nek[K], float logit[K],
    float* __restrict__ out, size_t p, int lane)
{
    #pragma unroll
    for (int k = 0; k < K; k++)
        logit[k] = warp_sum(logit[k]);

    float m = logit[0];
    #pragma unroll
    for (int k = 1; k < K; k++) m = fmaxf(m, logit[k]);
    float sum = 0.0f;
    float ex[K];
    #pragma unroll
    for (int k = 0; k < K; k++) { ex[k] = __expf(logit[k] - m); sum += ex[k]; }
    const float inv = 1.0f / sum;

    float4 acc = make_float4(0.f, 0.f, 0.f, 0.f);
    #pragma unroll
    for (int k = 0; k < K; k++) {
        const float a = ex[k] * inv;
        acc.x = fmaf(a, nek[k].x, acc.x);
        acc.y = fmaf(a, nek[k].y, acc.y);
        acc.z = fmaf(a, nek[k].z, acc.z);
        acc.w = fmaf(a, nek[k].w, acc.w);
    }

    float4* op = reinterpret_cast<float4*>(out + p * (2 * D));
    __stcs(op + lane, e4);
    __stcs(op + 32 + lane, acc);
}

__global__ void __launch_bounds__(THREADS, BLOCKS_PER_SM)
kgat_kernel(const float* __restrict__ ent,     // [P, 128]
            const float* __restrict__ ne,      // [P, K, 128]
            const float* __restrict__ nr,      // [P, K, 128]
            float* __restrict__ out,           // [P, 256]
            int total_pairs)
{
    const int warp0 = (blockIdx.x * blockDim.x + threadIdx.x) >> 5;
    const int lane  = threadIdx.x & 31;

    // Folded weight vectors: loaded once per warp
    const float4* vp = reinterpret_cast<const float4*>(g_v);
    const float4 v2 = __ldg(vp + lane);
    const float4 v3 = __ldg(vp + 32 + lane);

    for (int p = warp0; p < total_pairs; p += 2 * PERSIST_WARPS) {
        const int pA = p;
        const int pB = p + PERSIST_WARPS;
        const bool hasB = (pB < total_pairs);

        // ---- Front-batch all loads for BOTH pairs (up to 22 LDG.128) ----
        const float4* epA  = reinterpret_cast<const float4*>(ent + (size_t)pA * D);
        const float4* nepA = reinterpret_cast<const float4*>(ne + (size_t)pA * (K * D));
        const float4* nrpA = reinterpret_cast<const float4*>(nr + (size_t)pA * (K * D));

        const float4 e4A = __ldcs(epA + lane);
        float4 nekA[K];
        float  logA[K];
        #pragma unroll
        for (int k = 0; k < K; k++) {
            nekA[k]         = __ldcs(nepA + k * 32 + lane);
            const float4 r4 = __ldcs(nrpA + k * 32 + lane);
            logA[k] = dot4(nekA[k], v2) + dot4(r4, v3);
        }

        float4 e4B = make_float4(0.f, 0.f, 0.f, 0.f);
        float4 nekB[K];
        float  logB[K];
        if (hasB) {
            const float4* epB  = reinterpret_cast<const float4*>(ent + (size_t)pB * D);
            const float4* nepB = reinterpret_cast<const float4*>(ne + (size_t)pB * (K * D));
            const float4* nrpB = reinterpret_cast<const float4*>(nr + (size_t)pB * (K * D));
            e4B = __ldcs(epB + lane);
            #pragma unroll
            for (int k = 0; k < K; k++) {
                nekB[k]         = __ldcs(nepB + k * 32 + lane);
                const float4 r4 = __ldcs(nrpB + k * 32 + lane);
                logB[k] = dot4(nekB[k], v2) + dot4(r4, v3);
            }
        }

        // ---- Reduce / softmax / weighted-sum / store ----
        finish_pair(e4A, nekA, logA, out, (size_t)pA, lane);
        if (hasB)
            finish_pair(e4B, nekB, logB, out, (size_t)pB, lane);
    }
}

extern "C" void kernel_launch(void* const* d_in, const int* in_sizes, int n_in,
                              void* d_out, int out_size) {
    const float* ent = (const float*)d_in[0];   // entity_embedding   [B,N,128]
    const float* ne  = (const float*)d_in[1];   // neigh_entity       [B,N,5,128]
    const float* nr  = (const float*)d_in[2];   // neigh_relation     [B,N,5,128]
    const float* W1  = (const float*)d_in[3];   // [384,128]
    const float* W2  = (const float*)d_in[5];   // [128,1]
    float* out = (float*)d_out;

    const int total_pairs = in_sizes[0] / D;    // B*N

    fold_mlp_kernel<<<32, THREADS>>>(W1, W2);

    kgat_kernel<<<PERSIST_BLOCKS, THREADS>>>(ent, ne, nr, out, total_pairs);
}